// round 5
// baseline (speedup 1.0000x reference)
#include <cuda_runtime.h>
#include <cuda_fp16.h>
#include <cstdint>

#define NV    514
#define SDIM  512
#define MROWS 65536
#define EPSF  1e-16f

// ---------------------------------------------------------------------------
// Device scratch.
// g_B: R^T rows as fp16, PRE-SWIZZLED SMEM tile images:
//      [ntile(2)][chunk(8)] x 32768 B; each = 256(n) x 64(k) fp16, SW128.
// g_X: x converted to fp16, row-major [65536][512].
// ---------------------------------------------------------------------------
__device__ __align__(16) unsigned char g_B[2 * 8 * 32768];
__device__ __align__(16) __half g_X[(size_t)MROWS * SDIM];
__device__ float g_c[NV];

#define SW128(b) ((b) ^ (((b) >> 3) & 0x70))

__device__ __forceinline__ uint32_t smem_u32(const void* p) {
    uint32_t a;
    asm("{ .reg .u64 t; cvta.to.shared.u64 t, %1; cvt.u32.u64 %0, t; }"
        : "=r"(a) : "l"(p));
    return a;
}

// ===========================================================================
// Kernel 1: c_k = 2 / (||v_k||^2 + eps)
// ===========================================================================
__global__ void compute_c_kernel(const float* __restrict__ v) {
    const int k = blockIdx.x;
    const int t = threadIdx.x;
    const float* vk = v + k * SDIM;
    float s = 0.f;
    for (int i = t; i < SDIM; i += 128) { float a = vk[i]; s = fmaf(a, a, s); }
    #pragma unroll
    for (int o = 16; o > 0; o >>= 1) s += __shfl_xor_sync(0xffffffffu, s, o);
    __shared__ float red[4];
    if ((t & 31) == 0) red[t >> 5] = s;
    __syncthreads();
    if (t == 0) g_c[k] = 2.0f / (red[0] + red[1] + red[2] + red[3] + EPSF);
}

// ===========================================================================
// Kernel 2 (heterogeneous grid):
//   blocks [0,64):       reflector chain -> rows of R^T -> fp16 swizzled g_B
//   blocks [64,64+8192): convert x fp32 -> fp16 into g_X (16 elems/thread)
// ===========================================================================
#define CVT_BLOCKS 8192
__global__ __launch_bounds__(256) void prep_kernel(const float* __restrict__ v,
                                                   const float* __restrict__ x) {
    if (blockIdx.x >= 64) {
        // ---------------- convert x -> fp16 ----------------
        const size_t g = ((size_t)(blockIdx.x - 64) * 256 + threadIdx.x) * 16;
        const float4* src = (const float4*)(x + g);
        float4 f0 = src[0], f1 = src[1], f2 = src[2], f3 = src[3];
        __half2 h[8];
        h[0] = __floats2half2_rn(f0.x, f0.y); h[1] = __floats2half2_rn(f0.z, f0.w);
        h[2] = __floats2half2_rn(f1.x, f1.y); h[3] = __floats2half2_rn(f1.z, f1.w);
        h[4] = __floats2half2_rn(f2.x, f2.y); h[5] = __floats2half2_rn(f2.z, f2.w);
        h[6] = __floats2half2_rn(f3.x, f3.y); h[7] = __floats2half2_rn(f3.z, f3.w);
        uint4* dst = (uint4*)(g_X + g);
        dst[0] = make_uint4(*(uint32_t*)&h[0], *(uint32_t*)&h[1],
                            *(uint32_t*)&h[2], *(uint32_t*)&h[3]);
        dst[1] = make_uint4(*(uint32_t*)&h[4], *(uint32_t*)&h[5],
                            *(uint32_t*)&h[6], *(uint32_t*)&h[7]);
        return;
    }

    // ---------------- build R columns ----------------
    __shared__ float sc[NV];
    for (int i = threadIdx.x; i < NV; i += blockDim.x) sc[i] = g_c[i];
    __syncthreads();

    const int lane = threadIdx.x & 31;
    const int j = blockIdx.x * 8 + (threadIdx.x >> 5);   // column 0..511

    float r[16];
    #pragma unroll
    for (int i = 0; i < 16; ++i) r[i] = 0.f;
    {
        const int m = j >> 7;
        if (lane == ((j & 127) >> 2)) r[m * 4 + (j & 3)] = 1.0f;
    }

    const float4* v4 = (const float4*)v;
    float a[16], an[16];
    #pragma unroll
    for (int m = 0; m < 4; ++m) {
        float4 t = v4[m * 32 + lane];
        a[m*4+0]=t.x; a[m*4+1]=t.y; a[m*4+2]=t.z; a[m*4+3]=t.w;
    }

    for (int k = 0; k < NV; ++k) {
        float d0 = 0.f, d1 = 0.f, d2 = 0.f, d3 = 0.f;
        #pragma unroll
        for (int q = 0; q < 4; ++q) {
            d0 = fmaf(a[0*4+q], r[0*4+q], d0);
            d1 = fmaf(a[1*4+q], r[1*4+q], d1);
            d2 = fmaf(a[2*4+q], r[2*4+q], d2);
            d3 = fmaf(a[3*4+q], r[3*4+q], d3);
        }
        if (k + 1 < NV) {
            const float4* vn = v4 + (size_t)(k + 1) * 128;
            #pragma unroll
            for (int m = 0; m < 4; ++m) {
                float4 t = vn[m * 32 + lane];
                an[m*4+0]=t.x; an[m*4+1]=t.y; an[m*4+2]=t.z; an[m*4+3]=t.w;
            }
        }
        float d = (d0 + d1) + (d2 + d3);
        #pragma unroll
        for (int o = 16; o > 0; o >>= 1) d += __shfl_xor_sync(0xffffffffu, d, o);

        const float t = d * sc[k];
        #pragma unroll
        for (int i = 0; i < 16; ++i) r[i] = fmaf(-t, a[i], r[i]);
        #pragma unroll
        for (int i = 0; i < 16; ++i) a[i] = an[i];
    }

    const int ntile = j >> 8;
    const unsigned rowb = (unsigned)(j & 255) * 128u;
    #pragma unroll
    for (int m = 0; m < 4; ++m) {
        const int k0 = m * 128 + lane * 4;
        const int chunk = k0 >> 6;
        const unsigned off = rowb + (unsigned)((k0 & 63) * 2);
        const unsigned sw = SW128(off);

        __half2 p0 = __floats2half2_rn(r[m*4+0], r[m*4+1]);
        __half2 p1 = __floats2half2_rn(r[m*4+2], r[m*4+3]);
        uint2 H = make_uint2(*(uint32_t*)&p0, *(uint32_t*)&p1);
        *(uint2*)(g_B + (((size_t)ntile*8 + chunk) * 32768) + sw) = H;
    }
}

// ===========================================================================
// Kernel 3: out = x @ R via mma.sync fp16 (fp32 acc), pure cp.async pipeline.
// CTA 128x256, 8 warps (2m x 4n), warp tile 64x64, K-chunk 64, 3 stages.
// ===========================================================================
#define A_OFF 0
#define B_OFF 16384
#define STAGE_BYTES 49152
#define NSTAGE 3
#define GEMM_SMEM (1024 + NSTAGE * STAGE_BYTES)

__device__ __forceinline__ void ldsm4(uint32_t* r, uint32_t addr) {
    asm volatile("ldmatrix.sync.aligned.m8n8.x4.shared.b16 {%0,%1,%2,%3}, [%4];"
        : "=r"(r[0]), "=r"(r[1]), "=r"(r[2]), "=r"(r[3]) : "r"(addr));
}
__device__ __forceinline__ void mma16816(float* c, const uint32_t* a,
                                         uint32_t b0, uint32_t b1) {
    asm volatile(
        "mma.sync.aligned.m16n8k16.row.col.f32.f16.f16.f32 "
        "{%0,%1,%2,%3}, {%4,%5,%6,%7}, {%8,%9}, {%0,%1,%2,%3};"
        : "+f"(c[0]), "+f"(c[1]), "+f"(c[2]), "+f"(c[3])
        : "r"(a[0]), "r"(a[1]), "r"(a[2]), "r"(a[3]), "r"(b0), "r"(b1));
}
__device__ __forceinline__ void cpasync16(uint32_t dst, const void* src) {
    asm volatile("cp.async.cg.shared.global [%0], [%1], 16;"
        :: "r"(dst), "l"(src) : "memory");
}
#define CP_COMMIT() asm volatile("cp.async.commit_group;" ::: "memory")
#define CP_WAIT(n)  asm volatile("cp.async.wait_group %0;" :: "n"(n) : "memory")

__global__ __launch_bounds__(256, 1) void gemm_mma_kernel(float* __restrict__ out) {
    extern __shared__ char dsm[];
    char* smp = (char*)(((uintptr_t)dsm + 1023) & ~(uintptr_t)1023);
    const uint32_t sb = smem_u32(smp);

    const int tid = threadIdx.x;
    const int wid = tid >> 5;
    const int lane = tid & 31;
    const int wm = wid & 1;
    const int wn = wid >> 1;
    const int nt = blockIdx.x;
    const int bm = blockIdx.y << 7;

    // per-thread cp.async addressing
    const int arow = tid >> 1;                 // 0..127
    const int ahalf = (tid & 1) * 64;          // byte offset within 128B row
    const __half* aRowPtr = g_X + (size_t)(bm + arow) * SDIM;   // fp16 row
    const unsigned aBase = (unsigned)arow * 128u + (unsigned)ahalf;

    float c[4][8][4];
    #pragma unroll
    for (int i = 0; i < 4; ++i)
        #pragma unroll
        for (int jj = 0; jj < 8; ++jj)
            #pragma unroll
            for (int q = 0; q < 4; ++q) c[i][jj][q] = 0.f;

    // stage fill helper (A: 4x16B swizzled dst; B: 8x16B pre-swizzled copy)
    auto fill_stage = [&](int kc) {
        const uint32_t st = sb + (kc % NSTAGE) * STAGE_BYTES;
        const char* aSrc = (const char*)(aRowPtr + kc * 64) + ahalf;
        #pragma unroll
        for (int i = 0; i < 4; ++i)
            cpasync16(st + A_OFF + SW128(aBase + i * 16u), aSrc + i * 16);
        const char* bSrc = (const char*)(g_B + (((size_t)nt * 8 + kc) * 32768)) + tid * 16;
        #pragma unroll
        for (int i = 0; i < 8; ++i)
            cpasync16(st + B_OFF + tid * 16 + i * 4096, bSrc + i * 4096);
        CP_COMMIT();
    };

    // prologue: stages 0,1
    fill_stage(0);
    fill_stage(1);

    const int la = lane & 15;
    const int lh = lane >> 4;

    for (int kc = 0; kc < 8; ++kc) {
        if (kc == 7) { CP_WAIT(0); } else { CP_WAIT(1); }
        __syncthreads();                       // all readers of stage (kc-1)%3 done
        if (kc < 6) fill_stage(kc + 2);        // refill the stage freed at kc-1

        const uint32_t st = sb + (kc % NSTAGE) * STAGE_BYTES;
        #pragma unroll
        for (int ks = 0; ks < 4; ++ks) {
            uint32_t af[4][4], bf[4][4];
            #pragma unroll
            for (int mt = 0; mt < 4; ++mt) {
                const unsigned off = (unsigned)(wm*64 + mt*16 + la) * 128u
                                   + (unsigned)((lh*8 + ks*16) * 2);
                ldsm4(af[mt], st + A_OFF + SW128(off));
            }
            #pragma unroll
            for (int np = 0; np < 4; ++np) {
                const unsigned off = (unsigned)(wn*64 + np*16 + la) * 128u
                                   + (unsigned)((lh*8 + ks*16) * 2);
                ldsm4(bf[np], st + B_OFF + SW128(off));
            }
            #pragma unroll
            for (int mt = 0; mt < 4; ++mt)
                #pragma unroll
                for (int np = 0; np < 4; ++np) {
                    mma16816(c[mt][2*np],   af[mt], bf[np][0], bf[np][2]);
                    mma16816(c[mt][2*np+1], af[mt], bf[np][1], bf[np][3]);
                }
        }
        __syncthreads();                       // stage kc fully consumed
    }

    // epilogue
    const int r0 = bm + wm * 64 + (lane >> 2);
    const int c0 = (nt << 8) + wn * 64 + (lane & 3) * 2;
    #pragma unroll
    for (int mt = 0; mt < 4; ++mt) {
        #pragma unroll
        for (int ntl = 0; ntl < 8; ++ntl) {
            float* p0 = out + (size_t)(r0 + mt*16)     * SDIM + c0 + ntl*8;
            float* p1 = out + (size_t)(r0 + mt*16 + 8) * SDIM + c0 + ntl*8;
            *(float2*)p0 = make_float2(c[mt][ntl][0], c[mt][ntl][1]);
            *(float2*)p1 = make_float2(c[mt][ntl][2], c[mt][ntl][3]);
        }
    }
}

// ===========================================================================
extern "C" void kernel_launch(void* const* d_in, const int* in_sizes, int n_in,
                              void* d_out, int out_size) {
    const float* x = (const float*)d_in[0];   // [65536, 512]
    const float* v = (const float*)d_in[1];   // [514, 512, 1]
    float* out = (float*)d_out;               // [65536, 512]

    cudaFuncSetAttribute(gemm_mma_kernel, cudaFuncAttributeMaxDynamicSharedMemorySize, GEMM_SMEM);

    compute_c_kernel<<<NV, 128>>>(v);
    prep_kernel<<<64 + CVT_BLOCKS, 256>>>(v, x);
    dim3 grid(2, MROWS / 128);
    gemm_mma_kernel<<<grid, 256, GEMM_SMEM>>>(out);
}

// round 6
// speedup vs baseline: 1.4660x; 1.4660x over previous
#include <cuda_runtime.h>
#include <cuda_fp16.h>
#include <cstdint>

#define NV    514
#define SDIM  512
#define MROWS 65536
#define EPSF  1e-16f

// ---------------------------------------------------------------------------
// Device scratch.
// g_B: R^T rows as fp16, PRE-SWIZZLED SMEM tile images:
//      [ntile(2)][chunk(8)] x 32768 B; each = 256(n) x 64(k) fp16, SW128.
// g_X: x converted to fp16, row-major [65536][512].
// ---------------------------------------------------------------------------
__device__ __align__(16) unsigned char g_B[2 * 8 * 32768];
__device__ __align__(16) __half g_X[(size_t)MROWS * SDIM];
__device__ float g_c[NV];

#define SW128(b) ((b) ^ (((b) >> 3) & 0x70))

__device__ __forceinline__ uint32_t smem_u32(const void* p) {
    uint32_t a;
    asm("{ .reg .u64 t; cvta.to.shared.u64 t, %1; cvt.u32.u64 %0, t; }"
        : "=r"(a) : "l"(p));
    return a;
}

// ===========================================================================
// Kernel 1 (heterogeneous, all-parallel, no serial chains):
//   blocks [0, 8192):      convert x fp32 -> fp16 into g_X
//   blocks [8192, 8192+NV): c_k = 2/(||v_k||^2+eps)
// ===========================================================================
#define CVT_BLOCKS 8192
__global__ __launch_bounds__(256) void cvt_c_kernel(const float* __restrict__ x,
                                                    const float* __restrict__ v) {
    if (blockIdx.x < CVT_BLOCKS) {
        const size_t g = ((size_t)blockIdx.x * 256 + threadIdx.x) * 16;
        const float4* src = (const float4*)(x + g);
        float4 f0 = src[0], f1 = src[1], f2 = src[2], f3 = src[3];
        __half2 h[8];
        h[0] = __floats2half2_rn(f0.x, f0.y); h[1] = __floats2half2_rn(f0.z, f0.w);
        h[2] = __floats2half2_rn(f1.x, f1.y); h[3] = __floats2half2_rn(f1.z, f1.w);
        h[4] = __floats2half2_rn(f2.x, f2.y); h[5] = __floats2half2_rn(f2.z, f2.w);
        h[6] = __floats2half2_rn(f3.x, f3.y); h[7] = __floats2half2_rn(f3.z, f3.w);
        uint4* dst = (uint4*)(g_X + g);
        dst[0] = make_uint4(*(uint32_t*)&h[0], *(uint32_t*)&h[1],
                            *(uint32_t*)&h[2], *(uint32_t*)&h[3]);
        dst[1] = make_uint4(*(uint32_t*)&h[4], *(uint32_t*)&h[5],
                            *(uint32_t*)&h[6], *(uint32_t*)&h[7]);
        return;
    }
    // ---- compute c_k (256 threads, 2 elems each) ----
    const int k = blockIdx.x - CVT_BLOCKS;
    const int t = threadIdx.x;
    const float2 e = ((const float2*)(v + k * SDIM))[t];
    float s = fmaf(e.x, e.x, e.y * e.y);
    #pragma unroll
    for (int o = 16; o > 0; o >>= 1) s += __shfl_xor_sync(0xffffffffu, s, o);
    __shared__ float red[8];
    if ((t & 31) == 0) red[t >> 5] = s;
    __syncthreads();
    if (t == 0) {
        float tot = 0.f;
        #pragma unroll
        for (int i = 0; i < 8; ++i) tot += red[i];
        g_c[k] = 2.0f / (tot + EPSF);
    }
}

// ===========================================================================
// Kernel 2: reflector chain -> rows of R^T, emitted as fp16 into the
// pre-swizzled tile layout of g_B. One warp per column j. STANDALONE so the
// serial chain sees quiet L2 latency.
// ===========================================================================
__global__ __launch_bounds__(256) void build_R_kernel(const float* __restrict__ v) {
    __shared__ float sc[NV];
    for (int i = threadIdx.x; i < NV; i += blockDim.x) sc[i] = g_c[i];
    __syncthreads();

    const int lane = threadIdx.x & 31;
    const int j = blockIdx.x * 8 + (threadIdx.x >> 5);   // column 0..511

    float r[16];
    #pragma unroll
    for (int i = 0; i < 16; ++i) r[i] = 0.f;
    {
        const int m = j >> 7;
        if (lane == ((j & 127) >> 2)) r[m * 4 + (j & 3)] = 1.0f;
    }

    const float4* v4 = (const float4*)v;
    float a[16], an[16];
    #pragma unroll
    for (int m = 0; m < 4; ++m) {
        float4 t = v4[m * 32 + lane];
        a[m*4+0]=t.x; a[m*4+1]=t.y; a[m*4+2]=t.z; a[m*4+3]=t.w;
    }

    for (int k = 0; k < NV; ++k) {
        float d0 = 0.f, d1 = 0.f, d2 = 0.f, d3 = 0.f;
        #pragma unroll
        for (int q = 0; q < 4; ++q) {
            d0 = fmaf(a[0*4+q], r[0*4+q], d0);
            d1 = fmaf(a[1*4+q], r[1*4+q], d1);
            d2 = fmaf(a[2*4+q], r[2*4+q], d2);
            d3 = fmaf(a[3*4+q], r[3*4+q], d3);
        }
        if (k + 1 < NV) {
            const float4* vn = v4 + (size_t)(k + 1) * 128;
            #pragma unroll
            for (int m = 0; m < 4; ++m) {
                float4 t = vn[m * 32 + lane];
                an[m*4+0]=t.x; an[m*4+1]=t.y; an[m*4+2]=t.z; an[m*4+3]=t.w;
            }
        }
        float d = (d0 + d1) + (d2 + d3);
        #pragma unroll
        for (int o = 16; o > 0; o >>= 1) d += __shfl_xor_sync(0xffffffffu, d, o);

        const float t = d * sc[k];
        #pragma unroll
        for (int i = 0; i < 16; ++i) r[i] = fmaf(-t, a[i], r[i]);
        #pragma unroll
        for (int i = 0; i < 16; ++i) a[i] = an[i];
    }

    const int ntile = j >> 8;
    const unsigned rowb = (unsigned)(j & 255) * 128u;
    #pragma unroll
    for (int m = 0; m < 4; ++m) {
        const int k0 = m * 128 + lane * 4;
        const int chunk = k0 >> 6;
        const unsigned off = rowb + (unsigned)((k0 & 63) * 2);
        const unsigned sw = SW128(off);

        __half2 p0 = __floats2half2_rn(r[m*4+0], r[m*4+1]);
        __half2 p1 = __floats2half2_rn(r[m*4+2], r[m*4+3]);
        uint2 H = make_uint2(*(uint32_t*)&p0, *(uint32_t*)&p1);
        *(uint2*)(g_B + (((size_t)ntile*8 + chunk) * 32768) + sw) = H;
    }
}

// ===========================================================================
// Kernel 3: out = x @ R via mma.sync fp16 (fp32 acc), pure cp.async pipeline.
// CTA 128x256, 8 warps (2m x 4n), warp tile 64x64, K-chunk 64, 4 stages,
// single __syncthreads per mainloop iteration.
// ===========================================================================
#define A_OFF 0
#define B_OFF 16384
#define STAGE_BYTES 49152
#define NSTAGE 4
#define GEMM_SMEM (1024 + NSTAGE * STAGE_BYTES)

__device__ __forceinline__ void ldsm4(uint32_t* r, uint32_t addr) {
    asm volatile("ldmatrix.sync.aligned.m8n8.x4.shared.b16 {%0,%1,%2,%3}, [%4];"
        : "=r"(r[0]), "=r"(r[1]), "=r"(r[2]), "=r"(r[3]) : "r"(addr));
}
__device__ __forceinline__ void mma16816(float* c, const uint32_t* a,
                                         uint32_t b0, uint32_t b1) {
    asm volatile(
        "mma.sync.aligned.m16n8k16.row.col.f32.f16.f16.f32 "
        "{%0,%1,%2,%3}, {%4,%5,%6,%7}, {%8,%9}, {%0,%1,%2,%3};"
        : "+f"(c[0]), "+f"(c[1]), "+f"(c[2]), "+f"(c[3])
        : "r"(a[0]), "r"(a[1]), "r"(a[2]), "r"(a[3]), "r"(b0), "r"(b1));
}
__device__ __forceinline__ void cpasync16(uint32_t dst, const void* src) {
    asm volatile("cp.async.cg.shared.global [%0], [%1], 16;"
        :: "r"(dst), "l"(src) : "memory");
}
#define CP_COMMIT() asm volatile("cp.async.commit_group;" ::: "memory")
#define CP_WAIT(n)  asm volatile("cp.async.wait_group %0;" :: "n"(n) : "memory")

__global__ __launch_bounds__(256, 1) void gemm_mma_kernel(float* __restrict__ out) {
    extern __shared__ char dsm[];
    char* smp = (char*)(((uintptr_t)dsm + 1023) & ~(uintptr_t)1023);
    const uint32_t sb = smem_u32(smp);

    const int tid = threadIdx.x;
    const int wid = tid >> 5;
    const int lane = tid & 31;
    const int wm = wid & 1;
    const int wn = wid >> 1;
    const int nt = blockIdx.x;
    const int bm = blockIdx.y << 7;

    // per-thread cp.async addressing
    const int arow = tid >> 1;                 // 0..127
    const int ahalf = (tid & 1) * 64;          // byte offset within 128B row
    const __half* aRowPtr = g_X + (size_t)(bm + arow) * SDIM;
    const unsigned aBase = (unsigned)arow * 128u + (unsigned)ahalf;

    float c[4][8][4];
    #pragma unroll
    for (int i = 0; i < 4; ++i)
        #pragma unroll
        for (int jj = 0; jj < 8; ++jj)
            #pragma unroll
            for (int q = 0; q < 4; ++q) c[i][jj][q] = 0.f;

    auto fill_stage = [&](int kc) {
        const uint32_t st = sb + (kc % NSTAGE) * STAGE_BYTES;
        const char* aSrc = (const char*)(aRowPtr + kc * 64) + ahalf;
        #pragma unroll
        for (int i = 0; i < 4; ++i)
            cpasync16(st + A_OFF + SW128(aBase + i * 16u), aSrc + i * 16);
        const char* bSrc = (const char*)(g_B + (((size_t)nt * 8 + kc) * 32768)) + tid * 16;
        #pragma unroll
        for (int i = 0; i < 8; ++i)
            cpasync16(st + B_OFF + tid * 16 + i * 4096, bSrc + i * 4096);
        CP_COMMIT();
    };

    // prologue: stages 0,1,2
    fill_stage(0);
    fill_stage(1);
    fill_stage(2);

    const int la = lane & 15;
    const int lh = lane >> 4;

    for (int kc = 0; kc < 8; ++kc) {
        if (kc <= 5)      { CP_WAIT(2); }
        else if (kc == 6) { CP_WAIT(1); }
        else              { CP_WAIT(0); }
        __syncthreads();   // stage kc visible to all; stage (kc-1)%4 free
        if (kc < 5) fill_stage(kc + 3);

        const uint32_t st = sb + (kc % NSTAGE) * STAGE_BYTES;
        #pragma unroll
        for (int ks = 0; ks < 4; ++ks) {
            uint32_t af[4][4], bf[4][4];
            #pragma unroll
            for (int mt = 0; mt < 4; ++mt) {
                const unsigned off = (unsigned)(wm*64 + mt*16 + la) * 128u
                                   + (unsigned)((lh*8 + ks*16) * 2);
                ldsm4(af[mt], st + A_OFF + SW128(off));
            }
            #pragma unroll
            for (int np = 0; np < 4; ++np) {
                const unsigned off = (unsigned)(wn*64 + np*16 + la) * 128u
                                   + (unsigned)((lh*8 + ks*16) * 2);
                ldsm4(bf[np], st + B_OFF + SW128(off));
            }
            #pragma unroll
            for (int mt = 0; mt < 4; ++mt)
                #pragma unroll
                for (int np = 0; np < 4; ++np) {
                    mma16816(c[mt][2*np],   af[mt], bf[np][0], bf[np][2]);
                    mma16816(c[mt][2*np+1], af[mt], bf[np][1], bf[np][3]);
                }
        }
    }

    // epilogue
    const int r0 = bm + wm * 64 + (lane >> 2);
    const int c0 = (nt << 8) + wn * 64 + (lane & 3) * 2;
    #pragma unroll
    for (int mt = 0; mt < 4; ++mt) {
        #pragma unroll
        for (int ntl = 0; ntl < 8; ++ntl) {
            float* p0 = out + (size_t)(r0 + mt*16)     * SDIM + c0 + ntl*8;
            float* p1 = out + (size_t)(r0 + mt*16 + 8) * SDIM + c0 + ntl*8;
            *(float2*)p0 = make_float2(c[mt][ntl][0], c[mt][ntl][1]);
            *(float2*)p1 = make_float2(c[mt][ntl][2], c[mt][ntl][3]);
        }
    }
}

// ===========================================================================
extern "C" void kernel_launch(void* const* d_in, const int* in_sizes, int n_in,
                              void* d_out, int out_size) {
    const float* x = (const float*)d_in[0];   // [65536, 512]
    const float* v = (const float*)d_in[1];   // [514, 512, 1]
    float* out = (float*)d_out;               // [65536, 512]

    cudaFuncSetAttribute(gemm_mma_kernel, cudaFuncAttributeMaxDynamicSharedMemorySize, GEMM_SMEM);

    cvt_c_kernel<<<CVT_BLOCKS + NV, 256>>>(x, v);
    build_R_kernel<<<64, 256>>>(v);
    dim3 grid(2, MROWS / 128);
    gemm_mma_kernel<<<grid, 256, GEMM_SMEM>>>(out);
}

// round 7
// speedup vs baseline: 2.0055x; 1.3680x over previous
#include <cuda_runtime.h>
#include <cuda_fp16.h>
#include <cstdint>

#define NV    514
#define SDIM  512
#define MROWS 65536
#define EPSF  1e-16f

// ---------------------------------------------------------------------------
// Device scratch.
// g_B: R^T rows as fp16, PRE-SWIZZLED SMEM tile images:
//      [ntile(4)][chunk(8)] x 16384 B; each = 128(n) x 64(k) fp16, SW128.
// g_X: x converted to fp16, row-major [65536][512].
// ---------------------------------------------------------------------------
__device__ __align__(16) unsigned char g_B[4 * 8 * 16384];
__device__ __align__(16) __half g_X[(size_t)MROWS * SDIM];
__device__ float g_c[NV];

#define SW128(b) ((b) ^ (((b) >> 3) & 0x70))

__device__ __forceinline__ uint32_t smem_u32(const void* p) {
    uint32_t a;
    asm("{ .reg .u64 t; cvta.to.shared.u64 t, %1; cvt.u32.u64 %0, t; }"
        : "=r"(a) : "l"(p));
    return a;
}

// ===========================================================================
// Kernel 1: convert x -> fp16 (blocks [0,8192)) + c_k (blocks [8192,8192+NV))
// ===========================================================================
#define CVT_BLOCKS 8192
__global__ __launch_bounds__(256) void cvt_c_kernel(const float* __restrict__ x,
                                                    const float* __restrict__ v) {
    if (blockIdx.x < CVT_BLOCKS) {
        const size_t g = ((size_t)blockIdx.x * 256 + threadIdx.x) * 16;
        const float4* src = (const float4*)(x + g);
        float4 f0 = src[0], f1 = src[1], f2 = src[2], f3 = src[3];
        __half2 h[8];
        h[0] = __floats2half2_rn(f0.x, f0.y); h[1] = __floats2half2_rn(f0.z, f0.w);
        h[2] = __floats2half2_rn(f1.x, f1.y); h[3] = __floats2half2_rn(f1.z, f1.w);
        h[4] = __floats2half2_rn(f2.x, f2.y); h[5] = __floats2half2_rn(f2.z, f2.w);
        h[6] = __floats2half2_rn(f3.x, f3.y); h[7] = __floats2half2_rn(f3.z, f3.w);
        uint4* dst = (uint4*)(g_X + g);
        dst[0] = make_uint4(*(uint32_t*)&h[0], *(uint32_t*)&h[1],
                            *(uint32_t*)&h[2], *(uint32_t*)&h[3]);
        dst[1] = make_uint4(*(uint32_t*)&h[4], *(uint32_t*)&h[5],
                            *(uint32_t*)&h[6], *(uint32_t*)&h[7]);
        return;
    }
    const int k = blockIdx.x - CVT_BLOCKS;
    const int t = threadIdx.x;
    const float2 e = ((const float2*)(v + k * SDIM))[t];
    float s = fmaf(e.x, e.x, e.y * e.y);
    #pragma unroll
    for (int o = 16; o > 0; o >>= 1) s += __shfl_xor_sync(0xffffffffu, s, o);
    __shared__ float red[8];
    if ((t & 31) == 0) red[t >> 5] = s;
    __syncthreads();
    if (t == 0) {
        float tot = 0.f;
        #pragma unroll
        for (int i = 0; i < 8; ++i) tot += red[i];
        g_c[k] = 2.0f / (tot + EPSF);
    }
}

// ===========================================================================
// Kernel 2: reflector chain, 2 reflectors per iteration:
//   d = a_k.r ; p = a_{k+1}.r ; q = a_{k+1}.a_k   (3 dots, one shfl chain)
//   t0 = c_k d ; d2 = p - t0 q ; t1 = c_{k+1} d2
//   r -= t0 a_k + t1 a_{k+1}
// One warp per column j; emits fp16 pre-swizzled rows of R^T.
// ===========================================================================
__global__ __launch_bounds__(256) void build_R_kernel(const float* __restrict__ v) {
    __shared__ float sc[NV];
    for (int i = threadIdx.x; i < NV; i += blockDim.x) sc[i] = g_c[i];
    __syncthreads();

    const int lane = threadIdx.x & 31;
    const int j = blockIdx.x * 8 + (threadIdx.x >> 5);   // column 0..511

    float r[16];
    #pragma unroll
    for (int i = 0; i < 16; ++i) r[i] = 0.f;
    {
        const int m = j >> 7;
        if (lane == ((j & 127) >> 2)) r[m * 4 + (j & 3)] = 1.0f;
    }

    const float4* v4 = (const float4*)v;
    float a[16], b[16], an[16], bn[16];
    #pragma unroll
    for (int m = 0; m < 4; ++m) {
        float4 t0 = v4[m * 32 + lane];
        float4 t1 = v4[128 + m * 32 + lane];
        a[m*4+0]=t0.x; a[m*4+1]=t0.y; a[m*4+2]=t0.z; a[m*4+3]=t0.w;
        b[m*4+0]=t1.x; b[m*4+1]=t1.y; b[m*4+2]=t1.z; b[m*4+3]=t1.w;
    }

    for (int k = 0; k < NV; k += 2) {
        // three dot products (per-lane partials, independent chains)
        float d0=0.f,d1=0.f, p0=0.f,p1=0.f, q0=0.f,q1=0.f;
        #pragma unroll
        for (int i = 0; i < 16; i += 2) {
            d0 = fmaf(a[i],   r[i],   d0);
            d1 = fmaf(a[i+1], r[i+1], d1);
            p0 = fmaf(b[i],   r[i],   p0);
            p1 = fmaf(b[i+1], r[i+1], p1);
            q0 = fmaf(b[i],   a[i],   q0);
            q1 = fmaf(b[i+1], a[i+1], q1);
        }
        // prefetch next reflector pair
        if (k + 2 < NV) {
            const float4* va = v4 + (size_t)(k + 2) * 128;
            const float4* vb = v4 + (size_t)(k + 3) * 128;
            #pragma unroll
            for (int m = 0; m < 4; ++m) {
                float4 t0 = va[m * 32 + lane];
                float4 t1 = vb[m * 32 + lane];
                an[m*4+0]=t0.x; an[m*4+1]=t0.y; an[m*4+2]=t0.z; an[m*4+3]=t0.w;
                bn[m*4+0]=t1.x; bn[m*4+1]=t1.y; bn[m*4+2]=t1.z; bn[m*4+3]=t1.w;
            }
        }
        float d = d0 + d1, p = p0 + p1, q = q0 + q1;
        #pragma unroll
        for (int o = 16; o > 0; o >>= 1) {
            d += __shfl_xor_sync(0xffffffffu, d, o);
            p += __shfl_xor_sync(0xffffffffu, p, o);
            q += __shfl_xor_sync(0xffffffffu, q, o);
        }
        const float t0 = d * sc[k];
        const float t1 = fmaf(-t0, q, p) * sc[k + 1];
        #pragma unroll
        for (int i = 0; i < 16; ++i)
            r[i] = fmaf(-t1, b[i], fmaf(-t0, a[i], r[i]));
        #pragma unroll
        for (int i = 0; i < 16; ++i) { a[i] = an[i]; b[i] = bn[i]; }
    }

    const int ntile = j >> 7;                          // 4 n-tiles of 128
    const unsigned rowb = (unsigned)(j & 127) * 128u;
    #pragma unroll
    for (int m = 0; m < 4; ++m) {
        const int k0 = m * 128 + lane * 4;
        const int chunk = k0 >> 6;
        const unsigned off = rowb + (unsigned)((k0 & 63) * 2);
        const unsigned sw = SW128(off);
        __half2 p0 = __floats2half2_rn(r[m*4+0], r[m*4+1]);
        __half2 p1 = __floats2half2_rn(r[m*4+2], r[m*4+3]);
        uint2 H = make_uint2(*(uint32_t*)&p0, *(uint32_t*)&p1);
        *(uint2*)(g_B + (((size_t)ntile*8 + chunk) * 16384) + sw) = H;
    }
}

// ===========================================================================
// Kernel 3: out = x @ R via mma.sync fp16 (fp32 acc), pure cp.async pipeline.
// CTA 128x128, 8 warps (4m x 2n), warp tile 32x64, K-chunk 64, 3 stages,
// 2 CTAs/SM for bubble hiding.
// ===========================================================================
#define A_OFF 0
#define B_OFF 16384
#define STAGE_BYTES 32768
#define NSTAGE 3
#define GEMM_SMEM (1024 + NSTAGE * STAGE_BYTES)

__device__ __forceinline__ void ldsm4(uint32_t* r, uint32_t addr) {
    asm volatile("ldmatrix.sync.aligned.m8n8.x4.shared.b16 {%0,%1,%2,%3}, [%4];"
        : "=r"(r[0]), "=r"(r[1]), "=r"(r[2]), "=r"(r[3]) : "r"(addr));
}
__device__ __forceinline__ void mma16816(float* c, const uint32_t* a,
                                         uint32_t b0, uint32_t b1) {
    asm volatile(
        "mma.sync.aligned.m16n8k16.row.col.f32.f16.f16.f32 "
        "{%0,%1,%2,%3}, {%4,%5,%6,%7}, {%8,%9}, {%0,%1,%2,%3};"
        : "+f"(c[0]), "+f"(c[1]), "+f"(c[2]), "+f"(c[3])
        : "r"(a[0]), "r"(a[1]), "r"(a[2]), "r"(a[3]), "r"(b0), "r"(b1));
}
__device__ __forceinline__ void cpasync16(uint32_t dst, const void* src) {
    asm volatile("cp.async.cg.shared.global [%0], [%1], 16;"
        :: "r"(dst), "l"(src) : "memory");
}
#define CP_COMMIT() asm volatile("cp.async.commit_group;" ::: "memory")
#define CP_WAIT(n)  asm volatile("cp.async.wait_group %0;" :: "n"(n) : "memory")

__global__ __launch_bounds__(256, 2) void gemm_mma_kernel(float* __restrict__ out) {
    extern __shared__ char dsm[];
    char* smp = (char*)(((uintptr_t)dsm + 1023) & ~(uintptr_t)1023);
    const uint32_t sb = smem_u32(smp);

    const int tid = threadIdx.x;
    const int wid = tid >> 5;
    const int lane = tid & 31;
    const int wm = wid & 3;          // m offset wm*32
    const int wn = wid >> 2;         // n offset wn*64
    const int nt = blockIdx.x;       // 0..3
    const int bm = blockIdx.y << 7;
    const int bn = nt << 7;

    const int arow = tid >> 1;                 // 0..127
    const int ahalf = (tid & 1) * 64;          // byte offset within 128B row
    const __half* aRowPtr = g_X + (size_t)(bm + arow) * SDIM;
    const unsigned aBase = (unsigned)arow * 128u + (unsigned)ahalf;

    float c[2][8][4];
    #pragma unroll
    for (int i = 0; i < 2; ++i)
        #pragma unroll
        for (int jj = 0; jj < 8; ++jj)
            #pragma unroll
            for (int q = 0; q < 4; ++q) c[i][jj][q] = 0.f;

    auto fill_stage = [&](int kc) {
        const uint32_t st = sb + (kc % NSTAGE) * STAGE_BYTES;
        const char* aSrc = (const char*)(aRowPtr + kc * 64) + ahalf;
        #pragma unroll
        for (int i = 0; i < 4; ++i)
            cpasync16(st + A_OFF + SW128(aBase + i * 16u), aSrc + i * 16);
        const char* bSrc = (const char*)(g_B + (((size_t)nt * 8 + kc) * 16384)) + tid * 16;
        #pragma unroll
        for (int i = 0; i < 4; ++i)
            cpasync16(st + B_OFF + tid * 16 + i * 4096, bSrc + i * 4096);
        CP_COMMIT();
    };

    fill_stage(0);
    fill_stage(1);
    fill_stage(2);

    const int la = lane & 15;
    const int lh = lane >> 4;

    for (int kc = 0; kc < 8; ++kc) {
        if (kc <= 5)      { CP_WAIT(2); }
        else if (kc == 6) { CP_WAIT(1); }
        else              { CP_WAIT(0); }
        __syncthreads();                       // stage kc visible

        const uint32_t st = sb + (kc % NSTAGE) * STAGE_BYTES;
        #pragma unroll
        for (int ks = 0; ks < 4; ++ks) {
            uint32_t af[2][4], bf[4][4];
            #pragma unroll
            for (int mt = 0; mt < 2; ++mt) {
                const unsigned off = (unsigned)(wm*32 + mt*16 + la) * 128u
                                   + (unsigned)((lh*8 + ks*16) * 2);
                ldsm4(af[mt], st + A_OFF + SW128(off));
            }
            #pragma unroll
            for (int np = 0; np < 4; ++np) {
                const unsigned off = (unsigned)(wn*64 + np*16 + la) * 128u
                                   + (unsigned)((lh*8 + ks*16) * 2);
                ldsm4(bf[np], st + B_OFF + SW128(off));
            }
            #pragma unroll
            for (int mt = 0; mt < 2; ++mt)
                #pragma unroll
                for (int np = 0; np < 4; ++np) {
                    mma16816(c[mt][2*np],   af[mt], bf[np][0], bf[np][2]);
                    mma16816(c[mt][2*np+1], af[mt], bf[np][1], bf[np][3]);
                }
        }
        __syncthreads();                       // stage kc consumed
        if (kc < 5) fill_stage(kc + 3);
    }

    // epilogue
    const int r0 = bm + wm * 32 + (lane >> 2);
    const int c0 = bn + wn * 64 + (lane & 3) * 2;
    #pragma unroll
    for (int mt = 0; mt < 2; ++mt) {
        #pragma unroll
        for (int ntl = 0; ntl < 8; ++ntl) {
            float* p0 = out + (size_t)(r0 + mt*16)     * SDIM + c0 + ntl*8;
            float* p1 = out + (size_t)(r0 + mt*16 + 8) * SDIM + c0 + ntl*8;
            *(float2*)p0 = make_float2(c[mt][ntl][0], c[mt][ntl][1]);
            *(float2*)p1 = make_float2(c[mt][ntl][2], c[mt][ntl][3]);
        }
    }
}

// ===========================================================================
extern "C" void kernel_launch(void* const* d_in, const int* in_sizes, int n_in,
                              void* d_out, int out_size) {
    const float* x = (const float*)d_in[0];   // [65536, 512]
    const float* v = (const float*)d_in[1];   // [514, 512, 1]
    float* out = (float*)d_out;               // [65536, 512]

    cudaFuncSetAttribute(gemm_mma_kernel, cudaFuncAttributeMaxDynamicSharedMemorySize, GEMM_SMEM);

    cvt_c_kernel<<<CVT_BLOCKS + NV, 256>>>(x, v);
    build_R_kernel<<<64, 256>>>(v);
    dim3 grid(4, MROWS / 128);
    gemm_mma_kernel<<<grid, 256, GEMM_SMEM>>>(out);
}